// round 2
// baseline (speedup 1.0000x reference)
#include <cuda_runtime.h>
#include <cuda_bf16.h>
#include <cstdint>

// Problem constants (match reference)
#define Bn 128
#define Qn 200
#define Cn 92
#define NTHREADS 256
#define KMAX 7          // ceil(Qn/32) columns per lane
#define FINF 1e9f

struct Smem {
    float cost[Qn * Qn];   // cost[i*Qn + j]
    float u[Qn + 1];       // row potentials (1-based)
    int   p[Qn + 1];       // p[j] = row matched to column j (1-based), 0 = free
    int   way[Qn + 1];     // back-pointers (dumped from regs at row end)
    int   tc[Qn];
    float lse[Qn];
    float pb[Qn * 4];
    float tb[Qn * 4];
};

// monotone float<->uint key (total order preserved under unsigned compare)
__device__ __forceinline__ unsigned fkey(float f) {
    unsigned b = __float_as_uint(f);
    return (b & 0x80000000u) ? ~b : (b | 0x80000000u);
}
__device__ __forceinline__ float keyf(unsigned k) {
    unsigned b = (k & 0x80000000u) ? (k & 0x7fffffffu) : ~k;
    return __uint_as_float(b);
}

__global__ __launch_bounds__(NTHREADS, 1)
void hungarian_loss_kernel(const float* __restrict__ pred_cat,
                           const float* __restrict__ pred_bbox,
                           const int*   __restrict__ tar_cat,
                           const float* __restrict__ tar_bbox,
                           float* __restrict__ out) {
    extern __shared__ char smem_raw[];
    Smem* sm = reinterpret_cast<Smem*>(smem_raw);

    const int b    = blockIdx.x;
    const int tid  = threadIdx.x;
    const int lane = tid & 31;
    const int wid  = tid >> 5;

    // ---------------- Phase A: stage small tensors, per-row logsumexp -------
    for (int i = tid; i < Qn; i += NTHREADS) sm->tc[i] = tar_cat[b * Qn + i];
    for (int i = tid; i < Qn * 4; i += NTHREADS) {
        sm->pb[i] = pred_bbox[(size_t)b * Qn * 4 + i];
        sm->tb[i] = tar_bbox[(size_t)b * Qn * 4 + i];
    }
    for (int row = wid; row < Qn; row += (NTHREADS / 32)) {
        const float* x = pred_cat + ((size_t)b * Qn + row) * Cn;
        float m = -FINF;
        for (int c = lane; c < Cn; c += 32) m = fmaxf(m, x[c]);
        #pragma unroll
        for (int o = 16; o; o >>= 1) m = fmaxf(m, __shfl_xor_sync(0xFFFFFFFFu, m, o));
        float s = 0.f;
        for (int c = lane; c < Cn; c += 32) s += expf(x[c] - m);
        #pragma unroll
        for (int o = 16; o; o >>= 1) s += __shfl_xor_sync(0xFFFFFFFFu, s, o);
        if (lane == 0) sm->lse[row] = m + logf(s);
    }
    __syncthreads();

    // ---------------- Phase B: cost matrix into smem (all 8 warps) ----------
    for (int idx = tid; idx < Qn * Qn; idx += NTHREADS) {
        const int i = idx / Qn;
        const int j = idx - i * Qn;
        const int cls = sm->tc[j];
        const float ce = sm->lse[i] - pred_cat[((size_t)b * Qn + i) * Cn + cls];
        float sl1 = 0.f;
        #pragma unroll
        for (int k = 0; k < 4; k++) {
            const float d  = sm->pb[i * 4 + k] - sm->tb[j * 4 + k];
            const float ad = fabsf(d);
            sl1 += (ad < 1.f) ? 0.5f * d * d : (ad - 0.5f);
        }
        const float mask = (cls != 0) ? 1.f : 0.f;
        sm->cost[idx] = ce + sl1 * mask;
    }
    __syncthreads();

    // ---------------- warps 1..7 retire; warp 0 runs the solver -------------
    if (wid != 0) return;

    // init u, p (201 entries, lane-strided)
    #pragma unroll
    for (int k = 0; k < KMAX; k++) {
        const int idx = k * 32 + lane;
        if (idx <= Qn) { sm->u[idx] = 0.f; sm->p[idx] = 0; }
    }
    // column-owned register state: column j-1 = k*32+lane
    float v[KMAX], minv[KMAX];
    int   wayr[KMAX], prow[KMAX];
    #pragma unroll
    for (int k = 0; k < KMAX; k++) v[k] = 0.f;
    __syncwarp();

    for (int i = 1; i <= Qn; i++) {
        unsigned usedmask = 0;
        #pragma unroll
        for (int k = 0; k < KMAX; k++) { minv[k] = FINF; wayr[k] = 0; }
        int j0 = 0;
        int i0 = i;                     // p[j0=0] == i
        if (lane == 0) sm->p[0] = i;    // for augmentation walker (lane 0 only)

        for (;;) {
            // column j0 enters the tree; owning lane caches its matched row
            if (j0 > 0) {
                const int c = j0 - 1;
                if ((c & 31) == lane) {
                    usedmask |= 1u << (c >> 5);
                    prow[c >> 5] = i0;
                }
            }
            const float ui0 = sm->u[i0];
            const float* crow = sm->cost + (i0 - 1) * Qn;

            float bestv = FINF;
            int   bestc = Qn;
            #pragma unroll
            for (int k = 0; k < KMAX; k++) {
                const int col = k * 32 + lane;
                const bool act = (col < Qn) && !((usedmask >> k) & 1u);
                if (act) {
                    const float cur = crow[col] - ui0 - v[k];
                    if (cur < minv[k]) { minv[k] = cur; wayr[k] = j0; }
                    if (minv[k] < bestv) { bestv = minv[k]; bestc = col; }
                }
            }
            // cross-lane argmin: REDUX.MIN on monotone key + ballot + shfl
            const unsigned key  = fkey(bestv);
            const unsigned rmin = __reduce_min_sync(0xFFFFFFFFu, key);
            const unsigned ball = __ballot_sync(0xFFFFFFFFu, key == rmin);
            const int src  = __ffs(ball) - 1;
            const int j1   = __shfl_sync(0xFFFFFFFFu, bestc, src) + 1;
            const float delta = keyf(rmin);

            // potential updates
            #pragma unroll
            for (int k = 0; k < KMAX; k++) {
                const int col = k * 32 + lane;
                if (col < Qn) {
                    if ((usedmask >> k) & 1u) {
                        sm->u[prow[k]] += delta;   // distinct rows: race-free
                        v[k] -= delta;
                    } else {
                        minv[k] -= delta;
                    }
                }
            }
            if (lane == 0) sm->u[i] += delta;      // sentinel column 0 (row i)

            const int pj1 = sm->p[j1];             // p is frozen during Dijkstra
            __syncwarp();                          // u writes visible next iter
            j0 = j1;
            i0 = pj1;
            if (pj1 == 0) break;
        }

        // dump back-pointers, serial augmentation by lane 0
        #pragma unroll
        for (int k = 0; k < KMAX; k++) {
            const int col = k * 32 + lane;
            if (col < Qn) sm->way[col + 1] = wayr[k];
        }
        __syncwarp();
        if (lane == 0) {
            int j = j0;
            while (j) { const int jp = sm->way[j]; sm->p[j] = sm->p[jp]; j = jp; }
        }
        __syncwarp();
    }

    // ---------------- Phase D: gather matched costs -------------------------
    for (int j = lane + 1; j <= Qn; j += 32) {
        const int row = sm->p[j] - 1;
        out[b * Qn + row] = sm->cost[row * Qn + (j - 1)];
    }
}

extern "C" void kernel_launch(void* const* d_in, const int* in_sizes, int n_in,
                              void* d_out, int out_size) {
    const float* pred_cat  = (const float*)d_in[0];
    const float* pred_bbox = (const float*)d_in[1];
    const int*   tar_cat   = (const int*)d_in[2];
    const float* tar_bbox  = (const float*)d_in[3];
    float* out = (float*)d_out;

    static bool attr_set = false;
    if (!attr_set) {
        cudaFuncSetAttribute(hungarian_loss_kernel,
                             cudaFuncAttributeMaxDynamicSharedMemorySize,
                             (int)sizeof(Smem));
        attr_set = true;
    }
    hungarian_loss_kernel<<<Bn, NTHREADS, sizeof(Smem)>>>(
        pred_cat, pred_bbox, tar_cat, tar_bbox, out);
}

// round 3
// speedup vs baseline: 1.6427x; 1.6427x over previous
#include <cuda_runtime.h>
#include <cuda_bf16.h>
#include <cstdint>

#define Bn 128
#define Qn 200
#define Cn 92
#define NT 256
#define FINF 1e9f

struct Smem {
    float cost[Qn * Qn];   // cost[i*Qn + j]
    float v[Qn];           // column potentials
    int   y[Qn];           // y[j] = row matched to column j, -1 free
    int   x[Qn];           // x[i] = col matched to row i,    -1 free
    int   predsm[Qn];      // back-pointers (dumped before augment walk)
    int   frees[Qn];       // free-row worklist
    int   nfree;
    int   tc[Qn];
    float lse[Qn];
    float pb[Qn * 4];
    float tb[Qn * 4];
    unsigned rk[2][8];     // per-warp argmin key, double-buffered by parity
    int      rc[2][8];     // per-warp argmin column
};

// monotone float<->uint key (order preserved under unsigned compare)
__device__ __forceinline__ unsigned fkey(float f) {
    unsigned b = __float_as_uint(f);
    return (b & 0x80000000u) ? ~b : (b | 0x80000000u);
}
__device__ __forceinline__ float keyf(unsigned k) {
    unsigned b = (k & 0x80000000u) ? (k & 0x7fffffffu) : ~k;
    return __uint_as_float(b);
}

__global__ __launch_bounds__(NT, 1)
void hungarian_loss_kernel(const float* __restrict__ pred_cat,
                           const float* __restrict__ pred_bbox,
                           const int*   __restrict__ tar_cat,
                           const float* __restrict__ tar_bbox,
                           float* __restrict__ out) {
    extern __shared__ char smem_raw[];
    Smem* sm = reinterpret_cast<Smem*>(smem_raw);

    const int b    = blockIdx.x;
    const int tid  = threadIdx.x;
    const int lane = tid & 31;
    const int wid  = tid >> 5;

    // ---------------- Phase A: stage small tensors + per-row logsumexp ------
    if (tid == 0) sm->nfree = 0;
    for (int i = tid; i < Qn; i += NT) { sm->tc[i] = tar_cat[b * Qn + i]; sm->x[i] = -1; sm->y[i] = -1; }
    for (int i = tid; i < Qn * 4; i += NT) {
        sm->pb[i] = pred_bbox[(size_t)b * Qn * 4 + i];
        sm->tb[i] = tar_bbox[(size_t)b * Qn * 4 + i];
    }
    for (int row = wid; row < Qn; row += (NT / 32)) {
        const float* xr = pred_cat + ((size_t)b * Qn + row) * Cn;
        float m = -FINF;
        for (int c = lane; c < Cn; c += 32) m = fmaxf(m, xr[c]);
        #pragma unroll
        for (int o = 16; o; o >>= 1) m = fmaxf(m, __shfl_xor_sync(0xFFFFFFFFu, m, o));
        float s = 0.f;
        for (int c = lane; c < Cn; c += 32) s += expf(xr[c] - m);
        #pragma unroll
        for (int o = 16; o; o >>= 1) s += __shfl_xor_sync(0xFFFFFFFFu, s, o);
        if (lane == 0) sm->lse[row] = m + logf(s);
    }
    __syncthreads();

    // ---------------- Phase B: cost matrix into smem ------------------------
    for (int idx = tid; idx < Qn * Qn; idx += NT) {
        const int i = idx / Qn;
        const int j = idx - i * Qn;
        const int cls = sm->tc[j];
        const float ce = sm->lse[i] - pred_cat[((size_t)b * Qn + i) * Cn + cls];
        float sl1 = 0.f;
        #pragma unroll
        for (int k = 0; k < 4; k++) {
            const float d  = sm->pb[i * 4 + k] - sm->tb[j * 4 + k];
            const float ad = fabsf(d);
            sl1 += (ad < 1.f) ? 0.5f * d * d : (ad - 0.5f);
        }
        const float mask = (cls != 0) ? 1.f : 0.f;
        sm->cost[idx] = ce + sl1 * mask;
    }
    __syncthreads();

    // ---------------- Phase C1: column reduction + greedy tight match -------
    if (tid < Qn) {
        float mn = FINF; int ia = 0;
        for (int i = 0; i < Qn; i++) {
            const float val = sm->cost[i * Qn + tid];
            if (val < mn) { mn = val; ia = i; }
        }
        sm->v[tid] = mn;
        if (atomicCAS(&sm->x[ia], -1, tid) == -1) sm->y[tid] = ia;
    }
    __syncthreads();
    if (tid < Qn && sm->x[tid] == -1) {
        const int pos = atomicAdd(&sm->nfree, 1);
        sm->frees[pos] = tid;
    }
    __syncthreads();
    const int nf = sm->nfree;

    // ---------------- Phase C2: JV augmenting rows (1 barrier / iteration) --
    for (int fi = 0; fi < nf; fi++) {
        const int f = sm->frees[fi];

        float d    = FINF;
        int   pred = f;
        bool  todo = (tid < Qn);
        if (todo) d = sm->cost[f * Qn + tid] - sm->v[tid];

        int   t = 0;       // parity for slot double-buffering
        int   jsel;
        float dfin;

        for (;;) {
            // warp-level argmin of d over TODO columns
            const unsigned key  = todo ? fkey(d) : 0xFFFFFFFFu;
            const unsigned rmin = __reduce_min_sync(0xFFFFFFFFu, key);
            const unsigned ball = __ballot_sync(0xFFFFFFFFu, key == rmin);
            if (lane == 0) {
                sm->rk[t][wid] = rmin;
                sm->rc[t][wid] = (rmin == 0xFFFFFFFFu) ? 0x7fffffff
                                                       : (wid * 32 + (__ffs(ball) - 1));
            }
            __syncthreads();                          // the ONLY barrier per iter

            // redundant block-level min over 8 warp slots (broadcast reads)
            unsigned bk = 0xFFFFFFFFu; int bc = 0x7fffffff;
            #pragma unroll
            for (int w = 0; w < 8; w++) {
                const unsigned kk = sm->rk[t][w];
                const int      cc = sm->rc[t][w];
                if (kk < bk || (kk == bk && cc < bc)) { bk = kk; bc = cc; }
            }
            t ^= 1;
            const float delta = keyf(bk);
            const int   jstar = bc;

            if (tid == jstar) todo = false;           // pop j*
            const int irow = sm->y[jstar];            // broadcast
            if (irow < 0) { jsel = jstar; dfin = delta; break; }

            // h = u[irow] - delta, from tight matched edge (broadcast reads)
            const float h = sm->cost[irow * Qn + jstar] - sm->v[jstar] - delta;
            if (todo) {
                const float nd = sm->cost[irow * Qn + tid] - sm->v[tid] - h;
                if (nd < d) { d = nd; pred = irow; }
            }
        }

        // potentials update over popped columns + dump back-pointers
        if (tid < Qn) {
            sm->predsm[tid] = pred;
            if (!todo) sm->v[tid] += d - dfin;
        }
        __syncthreads();
        if (tid == 0) {                               // flip matching along path
            int j = jsel;
            for (;;) {
                const int i  = sm->predsm[j];
                sm->y[j] = i;
                const int jn = sm->x[i];
                sm->x[i] = j;
                if (i == f) break;
                j = jn;
            }
        }
        __syncthreads();
    }

    // ---------------- Phase D: gather matched costs -------------------------
    for (int j = tid; j < Qn; j += NT) {
        const int row = sm->y[j];
        out[b * Qn + row] = sm->cost[row * Qn + j];
    }
}

extern "C" void kernel_launch(void* const* d_in, const int* in_sizes, int n_in,
                              void* d_out, int out_size) {
    const float* pred_cat  = (const float*)d_in[0];
    const float* pred_bbox = (const float*)d_in[1];
    const int*   tar_cat   = (const int*)d_in[2];
    const float* tar_bbox  = (const float*)d_in[3];
    float* out = (float*)d_out;

    static bool attr_set = false;
    if (!attr_set) {
        cudaFuncSetAttribute(hungarian_loss_kernel,
                             cudaFuncAttributeMaxDynamicSharedMemorySize,
                             (int)sizeof(Smem));
        attr_set = true;
    }
    hungarian_loss_kernel<<<Bn, NT, sizeof(Smem)>>>(
        pred_cat, pred_bbox, tar_cat, tar_bbox, out);
}